// round 13
// baseline (speedup 1.0000x reference)
#include <cuda_runtime.h>
#include <cuda_bf16.h>
#include <cuda_fp16.h>
#include <cuda_fp8.h>
#include <math.h>
#include <stdint.h>

// Problem constants
#define BATCH   4
#define SEQ     8192
#define MROWS   (BATCH * SEQ)   // 32768
#define DIM     256
#define NCLS    1000
#define EPS_F   1e-5f

#define BK  32
#define LDT 40                  // proj: 80B padded row (bf16)

// Proj: CTA 128x256, 16 warps (4M x 4N), warp 32x64. W resident in smem.
#define PM 128
#define W_CHUNK_H (256 * LDT)
#define A_STG_H   (PM * LDT)
#define PROJ_SMEM ((8 * W_CHUNK_H + 2 * A_STG_H) * 2)   // 184320 B

// Logits (fp8): 128x128 CTA, 8 warps (4M x 2N), warp 32x64.
// Full K=256 resident per operand: 128 rows x 272B (256 data + 16 pad).
#define BM 128
#define BN 128
#define LDTQ 136                               // b16 units per row (272 B)
#define Q_ROW_B 272
#define Q_STG_BYTES (BM * Q_ROW_B)             // 34816 B
#define LOGITS_SMEM (2 * Q_STG_BYTES)          // 69632 B

#define XSCALE 16.0f                           // fp8 pre-scale (power of 2)
#define INV_XSCALE2 (1.0f / 256.0f)

// Scratch
__device__ uint8_t g_xq[MROWS * DIM];          // expmapped features (e4m3, x16)
__device__ float   g_xsq[MROWS];
__device__ uint8_t g_pq[NCLS * DIM];           // expmapped prototypes (e4m3, x16)
__device__ float   g_psq[NCLS];

// ---------------------------------------------------------------------------
// PTX helpers (base-sm_103-legal only)
// ---------------------------------------------------------------------------
__device__ __forceinline__ uint32_t smem_u32(const void* p) {
    return (uint32_t)__cvta_generic_to_shared(p);
}
__device__ __forceinline__ void cp16s(uint32_t dst_saddr, const void* src, bool valid)
{
    int sz = valid ? 16 : 0;
    asm volatile("cp.async.cg.shared.global [%0], [%1], 16, %2;\n"
                 :: "r"(dst_saddr), "l"(src), "r"(sz));
}
#define CP_COMMIT() asm volatile("cp.async.commit_group;\n" ::: "memory")
#define CP_WAIT0()  asm volatile("cp.async.wait_group 0;\n" ::: "memory")

__device__ __forceinline__ void ldm_x4(uint32_t& r0, uint32_t& r1,
                                       uint32_t& r2, uint32_t& r3, uint32_t saddr)
{
    asm volatile("ldmatrix.sync.aligned.m8n8.x4.shared.b16 {%0,%1,%2,%3}, [%4];"
                 : "=r"(r0), "=r"(r1), "=r"(r2), "=r"(r3) : "r"(saddr));
}

// bf16 inputs, fp32 accumulate (proj)
__device__ __forceinline__ void mma16816(float acc[4], uint32_t a0, uint32_t a1,
                                         uint32_t a2, uint32_t a3,
                                         uint32_t b0, uint32_t b1)
{
    asm volatile(
        "mma.sync.aligned.m16n8k16.row.col.f32.bf16.bf16.f32 "
        "{%0,%1,%2,%3}, {%4,%5,%6,%7}, {%8,%9}, {%0,%1,%2,%3};\n"
        : "+f"(acc[0]), "+f"(acc[1]), "+f"(acc[2]), "+f"(acc[3])
        : "r"(a0), "r"(a1), "r"(a2), "r"(a3), "r"(b0), "r"(b1));
}

// e4m3 inputs, fp32 accumulate, K=32 per issue (logits)
__device__ __forceinline__ void mma16832q(float acc[4], uint32_t a0, uint32_t a1,
                                          uint32_t a2, uint32_t a3,
                                          uint32_t b0, uint32_t b1)
{
    asm volatile(
        "mma.sync.aligned.m16n8k32.row.col.f32.e4m3.e4m3.f32 "
        "{%0,%1,%2,%3}, {%4,%5,%6,%7}, {%8,%9}, {%0,%1,%2,%3};\n"
        : "+f"(acc[0]), "+f"(acc[1]), "+f"(acc[2]), "+f"(acc[3])
        : "r"(a0), "r"(a1), "r"(a2), "r"(a3), "r"(b0), "r"(b1));
}

__device__ __forceinline__ float fsqrt_approx(float x) {
    float y;
    asm("sqrt.approx.f32 %0, %1;" : "=f"(y) : "f"(x));
    return y;
}

__device__ __forceinline__ uint16_t pack_fp8x2(float a, float b) {
    __nv_fp8x2_e4m3 q(make_float2(a, b));
    return *(uint16_t*)&q;
}

// ---------------------------------------------------------------------------
// Proj: xq = fp8(expmap0(features @ W^T + b) * 16). W resident in smem (bf16).
// ---------------------------------------------------------------------------
__global__ __launch_bounds__(512, 1)
void proj_expmap_kernel(const float* __restrict__ A,
                        const float* __restrict__ W,
                        const float* __restrict__ bias,
                        uint8_t* __restrict__ Xq,
                        float* __restrict__ xsq_out)
{
    extern __shared__ __nv_bfloat16 dsm[];
    const uint32_t wbase = smem_u32(dsm);
    const uint32_t abase = wbase + 8u * W_CHUNK_H * 2u;
    __shared__ float rowsum[PM];
    __shared__ float rowscale[PM];

    const int tid = threadIdx.x;
    const int m0  = blockIdx.x * PM;
    if (tid < PM) rowsum[tid] = 0.f;

    const int warp = tid >> 5;
    const int lane = tid & 31;
    const int wm = (warp & 3) * 32;
    const int wn = (warp >> 2) * 64;
    const int g  = lane >> 2;
    const int tg = lane & 3;
    const int lrow16 = lane & 15;
    const int khalf  = (lane >> 4) << 3;

    #pragma unroll
    for (int it = 0; it < 32; it++) {
        int idx = tid + it * 512;
        int r = idx >> 6;
        int c4 = (idx & 63) * 4;
        float4 v = *(const float4*)&W[(size_t)r * DIM + c4];
        __nv_bfloat162 lo = __floats2bfloat162_rn(v.x, v.y);
        __nv_bfloat162 hi = __floats2bfloat162_rn(v.z, v.w);
        uint2 pk; pk.x = *(uint32_t*)&lo; pk.y = *(uint32_t*)&hi;
        int chunk = c4 >> 5;
        int cc = c4 & 31;
        *(uint2*)(dsm + (size_t)(chunk * 256 + r) * LDT + cc) = pk;
    }

    float4 apf[2];
    {
        #pragma unroll
        for (int r = 0; r < 2; r++) {
            int idx = tid + r * 512;
            int row = idx >> 3;
            int cc = (idx & 7) * 4;
            apf[r] = *(const float4*)&A[(size_t)(m0 + row) * DIM + 0 + cc];
        }
    }
    __syncthreads();

    float acc[2][8][4];
    #pragma unroll
    for (int i = 0; i < 2; i++)
        #pragma unroll
        for (int j = 0; j < 8; j++)
            #pragma unroll
            for (int e = 0; e < 4; e++) acc[i][j][e] = 0.f;

    for (int kt = 0; kt < 8; kt++) {
        const uint32_t ast = abase + (uint32_t)((kt & 1) * A_STG_H) * 2u;
        #pragma unroll
        for (int r = 0; r < 2; r++) {
            int idx = tid + r * 512;
            int row = idx >> 3;
            int cc = (idx & 7) * 4;
            __nv_bfloat162 lo = __floats2bfloat162_rn(apf[r].x, apf[r].y);
            __nv_bfloat162 hi = __floats2bfloat162_rn(apf[r].z, apf[r].w);
            uint2 pk; pk.x = *(uint32_t*)&lo; pk.y = *(uint32_t*)&hi;
            *(uint2*)(dsm + (size_t)(8 * W_CHUNK_H) + (size_t)((kt & 1) * PM + row) * LDT + cc) = pk;
        }
        __syncthreads();

        if (kt < 7) {
            const int k0 = (kt + 1) * BK;
            #pragma unroll
            for (int r = 0; r < 2; r++) {
                int idx = tid + r * 512;
                int row = idx >> 3;
                int cc = (idx & 7) * 4;
                apf[r] = *(const float4*)&A[(size_t)(m0 + row) * DIM + k0 + cc];
            }
        }

        const uint32_t bb = wbase + (uint32_t)(kt * W_CHUNK_H) * 2u;
        #pragma unroll
        for (int ks = 0; ks < 2; ks++) {
            const int kc = ks * 16 + khalf;
            uint32_t a[2][4];
            #pragma unroll
            for (int i = 0; i < 2; i++)
                ldm_x4(a[i][0], a[i][1], a[i][2], a[i][3],
                       ast + (uint32_t)((wm + i * 16 + lrow16) * LDT + kc) * 2u);
            #pragma unroll
            for (int jj = 0; jj < 4; jj++) {
                uint32_t b0, b1, b2, b3;
                ldm_x4(b0, b1, b2, b3,
                       bb + (uint32_t)((wn + jj * 16 + lrow16) * LDT + kc) * 2u);
                #pragma unroll
                for (int i = 0; i < 2; i++) {
                    mma16816(acc[i][2 * jj + 0], a[i][0], a[i][1], a[i][2], a[i][3], b0, b2);
                    mma16816(acc[i][2 * jj + 1], a[i][0], a[i][1], a[i][2], a[i][3], b1, b3);
                }
            }
        }
        __syncthreads();
    }

    float part[2][2] = {{0.f, 0.f}, {0.f, 0.f}};
    #pragma unroll
    for (int j = 0; j < 8; j++) {
        const int nb = wn + j * 8 + tg * 2;
        const float b0 = bias[nb], b1 = bias[nb + 1];
        #pragma unroll
        for (int i = 0; i < 2; i++) {
            #pragma unroll
            for (int h = 0; h < 2; h++) {
                float y0 = acc[i][j][2 * h + 0] + b0;
                float y1 = acc[i][j][2 * h + 1] + b1;
                acc[i][j][2 * h + 0] = y0;
                acc[i][j][2 * h + 1] = y1;
                part[i][h] += y0 * y0 + y1 * y1;
            }
        }
    }
    #pragma unroll
    for (int i = 0; i < 2; i++)
        #pragma unroll
        for (int h = 0; h < 2; h++)
            atomicAdd(&rowsum[wm + i * 16 + g + h * 8], part[i][h]);
    __syncthreads();

    if (tid < PM) {
        const float total = rowsum[tid];
        const float norm  = sqrtf(total);
        const float cn    = fmaxf(norm, EPS_F);
        const float s     = tanhf(cn) / cn;
        rowscale[tid] = s * XSCALE;
        xsq_out[m0 + tid] = s * s * total;
    }
    __syncthreads();

    #pragma unroll
    for (int i = 0; i < 2; i++) {
        #pragma unroll
        for (int h = 0; h < 2; h++) {
            const int ml = wm + i * 16 + g + h * 8;
            const float s = rowscale[ml];
            const int m = m0 + ml;
            #pragma unroll
            for (int j = 0; j < 8; j++) {
                const int nb = wn + j * 8 + tg * 2;
                uint16_t q = pack_fp8x2(s * acc[i][j][2 * h + 0],
                                        s * acc[i][j][2 * h + 1]);
                *(uint16_t*)&Xq[(size_t)m * DIM + nb] = q;
            }
        }
    }
}

// ---------------------------------------------------------------------------
// expmap0 for embeddings (fp32 -> e4m3 x16 + ||p||^2)
// ---------------------------------------------------------------------------
__global__ void expmap_kernel(const float* __restrict__ src,
                              uint8_t* __restrict__ dst,
                              float* __restrict__ sq_out)
{
    const int row = blockIdx.x;
    const int tid = threadIdx.x;       // 128 threads, 2 elems each
    const float v0 = src[(size_t)row * DIM + tid * 2 + 0];
    const float v1 = src[(size_t)row * DIM + tid * 2 + 1];

    float s = v0 * v0 + v1 * v1;
    #pragma unroll
    for (int off = 16; off > 0; off >>= 1)
        s += __shfl_xor_sync(0xFFFFFFFFu, s, off);

    __shared__ float warp_s[4];
    __shared__ float total_sh;
    const int warp = tid >> 5;
    if ((tid & 31) == 0) warp_s[warp] = s;
    __syncthreads();
    if (tid == 0) {
        float t = 0.f;
        #pragma unroll
        for (int w = 0; w < 4; w++) t += warp_s[w];
        total_sh = t;
    }
    __syncthreads();

    const float total = total_sh;
    const float norm  = sqrtf(total);
    const float cn    = fmaxf(norm, EPS_F);
    const float scale = tanhf(cn) / cn;

    uint16_t q = pack_fp8x2(scale * XSCALE * v0, scale * XSCALE * v1);
    *(uint16_t*)&dst[(size_t)row * DIM + tid * 2] = q;
    if (tid == 0) sq_out[row] = scale * scale * total;
}

// ---------------------------------------------------------------------------
// Logits GEMM: fp8 e4m3 m16n8k32, full-K resident (no pipeline), fp32 acc,
// approx Poincare epilogue.
// ---------------------------------------------------------------------------
__global__ __launch_bounds__(256, 2)
void logits_mma_kernel(const uint8_t* __restrict__ Xq,
                       const uint8_t* __restrict__ Pq,
                       const float* __restrict__ xsq,
                       const float* __restrict__ psq,
                       const float* __restrict__ logit_scale,
                       float* __restrict__ Out)
{
    extern __shared__ uint8_t qsm[];
    const uint32_t abase = smem_u32(qsm);                 // A: 128 x 272B
    const uint32_t bbase = abase + Q_STG_BYTES;           // B: 128 x 272B

    const int tid  = threadIdx.x;
    const int m0 = blockIdx.y * BM;
    const int n0 = blockIdx.x * BN;

    const int warp = tid >> 5;
    const int lane = tid & 31;
    const int wm = (warp & 3) * 32;
    const int wn = (warp >> 2) * 64;
    const int g  = lane >> 2;
    const int tg = lane & 3;
    const int lrow16 = lane & 15;
    const int khalf  = (lane >> 4) << 3;   // b16 units

    // ---- load both operands full-K: 2048 x 16B chunks each, 8/thread
    #pragma unroll
    for (int r = 0; r < 8; r++) {
        int idx = tid + r * 256;
        int row = idx >> 4;
        int cb  = (idx & 15) * 16;    // byte offset within 256B row
        cp16s(abase + (uint32_t)(row * Q_ROW_B + cb),
              &Xq[(size_t)(m0 + row) * DIM + cb], true);
        cp16s(bbase + (uint32_t)(row * Q_ROW_B + cb),
              &Pq[(size_t)(n0 + row) * DIM + cb], (n0 + row) < NCLS);
    }
    CP_COMMIT();

    float acc[2][8][4];
    #pragma unroll
    for (int i = 0; i < 2; i++)
        #pragma unroll
        for (int j = 0; j < 8; j++)
            #pragma unroll
            for (int e = 0; e < 4; e++) acc[i][j][e] = 0.f;

    CP_WAIT0();
    __syncthreads();

    // ---- 8 k32 steps, no barriers inside
    #pragma unroll
    for (int ks = 0; ks < 8; ks++) {
        const int kc = ks * 16 + khalf;    // b16 col
        uint32_t a[2][4];
        #pragma unroll
        for (int i = 0; i < 2; i++)
            ldm_x4(a[i][0], a[i][1], a[i][2], a[i][3],
                   abase + (uint32_t)((wm + i * 16 + lrow16) * LDTQ + kc) * 2u);
        #pragma unroll
        for (int jj = 0; jj < 4; jj++) {
            uint32_t b0, b1, b2, b3;
            ldm_x4(b0, b1, b2, b3,
                   bbase + (uint32_t)((wn + jj * 16 + lrow16) * LDTQ + kc) * 2u);
            #pragma unroll
            for (int i = 0; i < 2; i++) {
                mma16832q(acc[i][2 * jj + 0], a[i][0], a[i][1], a[i][2], a[i][3], b0, b2);
                mma16832q(acc[i][2 * jj + 1], a[i][0], a[i][1], a[i][2], a[i][3], b1, b3);
            }
        }
    }

    // ---- Poincare epilogue (approx MUFU math); un-scale by 1/256
    const float lscale = fminf(expf(logit_scale[0]), 100.f);

    float xs[2][2], one_m_xs[2][2];
    #pragma unroll
    for (int i = 0; i < 2; i++)
        #pragma unroll
        for (int h = 0; h < 2; h++) {
            const int m = m0 + wm + i * 16 + g + h * 8;
            xs[i][h] = xsq[m];
            one_m_xs[i][h] = 1.f - xs[i][h];
        }

    #pragma unroll
    for (int j = 0; j < 8; j++) {
        const int nb = n0 + wn + j * 8 + tg * 2;
        if (nb >= NCLS) continue;              // NCLS even -> pairs in/out together
        const float ps0 = psq[nb], ps1 = psq[nb + 1];
        const float omp0 = 1.f - ps0, omp1 = 1.f - ps1;
        #pragma unroll
        for (int i = 0; i < 2; i++) {
            #pragma unroll
            for (int h = 0; h < 2; h++) {
                const int m = m0 + wm + i * 16 + g + h * 8;
                const float xsv = xs[i][h];
                const float omx = one_m_xs[i][h];

                const float xp0 = acc[i][j][2 * h + 0] * INV_XSCALE2;
                const float xp1 = acc[i][j][2 * h + 1] * INV_XSCALE2;
                float d0 = fmaxf(xsv + ps0 - 2.f * xp0, 0.f);
                float d1 = fmaxf(xsv + ps1 - 2.f * xp1, 0.f);
                float de0 = fmaxf(omx * omp0, EPS_F);
                float de1 = fmaxf(omx * omp1, EPS_F);
                float a0 = fmaxf(fmaf(2.f, __fdividef(d0, de0), 1.f), 1.f + EPS_F);
                float a1 = fmaxf(fmaf(2.f, __fdividef(d1, de1), 1.f), 1.f + EPS_F);
                float r0 = __logf(a0 + fsqrt_approx(fmaf(a0, a0, -1.f)));
                float r1 = __logf(a1 + fsqrt_approx(fmaf(a1, a1, -1.f)));
                float2 v = make_float2(-r0 * lscale, -r1 * lscale);
                *(float2*)&Out[(size_t)m * NCLS + nb] = v;
            }
        }
    }
}

// ---------------------------------------------------------------------------
// Launch
// ---------------------------------------------------------------------------
extern "C" void kernel_launch(void* const* d_in, const int* in_sizes, int n_in,
                              void* d_out, int out_size)
{
    const float* features    = (const float*)d_in[0];
    const float* W           = (const float*)d_in[1];
    const float* bias        = (const float*)d_in[2];
    const float* embeddings  = (const float*)d_in[3];
    const float* logit_scale = (const float*)d_in[4];
    float* out = (float*)d_out;

    uint8_t *xq, *pq;
    float *xsq, *psq;
    cudaGetSymbolAddress((void**)&xq,  g_xq);
    cudaGetSymbolAddress((void**)&xsq, g_xsq);
    cudaGetSymbolAddress((void**)&pq,  g_pq);
    cudaGetSymbolAddress((void**)&psq, g_psq);

    // 1. Fused proj (W-resident smem) + expmap -> xq (fp8 x16), xsq
    cudaFuncSetAttribute(proj_expmap_kernel,
                         cudaFuncAttributeMaxDynamicSharedMemorySize, PROJ_SMEM);
    proj_expmap_kernel<<<MROWS / PM, 512, PROJ_SMEM>>>(features, W, bias, xq, xsq);

    // 2. expmap0 on embeddings -> pq (fp8 x16), psq
    expmap_kernel<<<NCLS, 128>>>(embeddings, pq, psq);

    // 3. Logits GEMM (fp8 m16n8k32, full-K resident) + approx Poincare epilogue
    cudaFuncSetAttribute(logits_mma_kernel,
                         cudaFuncAttributeMaxDynamicSharedMemorySize, LOGITS_SMEM);
    {
        dim3 grid((NCLS + BN - 1) / BN, MROWS / BM);   // (8, 256)
        logits_mma_kernel<<<grid, 256, LOGITS_SMEM>>>(xq, pq, xsq, psq,
                                                      logit_scale, out);
    }
}

// round 15
// speedup vs baseline: 1.0131x; 1.0131x over previous
#include <cuda_runtime.h>
#include <cuda_bf16.h>
#include <cuda_fp16.h>
#include <cuda_fp8.h>
#include <math.h>
#include <stdint.h>

// Problem constants
#define BATCH   4
#define SEQ     8192
#define MROWS   (BATCH * SEQ)   // 32768
#define DIM     256
#define NCLS    1000
#define EPS_F   1e-5f
#define INV_EPS 1e5f

#define BK  32
#define LDT 40                  // proj: 80B padded row (bf16)

// Proj: CTA 128x256, 16 warps (4M x 4N), warp 32x64. W resident in smem.
#define PM 128
#define W_CHUNK_H (256 * LDT)
#define A_STG_H   (PM * LDT)
#define PROJ_SMEM ((8 * W_CHUNK_H + 2 * A_STG_H) * 2)   // 184320 B

// Logits (fp8): 128x128 CTA, 8 warps (4M x 2N), warp 32x64.
// 2-stage K pipeline, BK=128 fp8 bytes per stage.
#define BM 128
#define BN 128
#define BKQ 128                                // fp8 elems per stage
#define LDTQ 72                                // b16 units per row (144 B)
#define Q_ROW_B 144
#define Q_STG_BYTES (BM * Q_ROW_B)             // 18432 B
#define LOGITS_SMEM (4 * Q_STG_BYTES)          // 73728 B

#define XSCALE 16.0f                           // fp8 pre-scale (power of 2)
#define INV_XSCALE2 (1.0f / 256.0f)

// Scratch
__device__ uint8_t g_xq[MROWS * DIM];          // expmapped features (e4m3, x16)
__device__ float   g_xsq[MROWS];
__device__ uint8_t g_pq[NCLS * DIM];           // expmapped prototypes (e4m3, x16)
__device__ float   g_psq[NCLS];

// ---------------------------------------------------------------------------
// PTX helpers (base-sm_103-legal only)
// ---------------------------------------------------------------------------
__device__ __forceinline__ uint32_t smem_u32(const void* p) {
    return (uint32_t)__cvta_generic_to_shared(p);
}
__device__ __forceinline__ void cp16s(uint32_t dst_saddr, const void* src, bool valid)
{
    int sz = valid ? 16 : 0;
    asm volatile("cp.async.cg.shared.global [%0], [%1], 16, %2;\n"
                 :: "r"(dst_saddr), "l"(src), "r"(sz));
}
#define CP_COMMIT() asm volatile("cp.async.commit_group;\n" ::: "memory")

__device__ __forceinline__ void ldm_x4(uint32_t& r0, uint32_t& r1,
                                       uint32_t& r2, uint32_t& r3, uint32_t saddr)
{
    asm volatile("ldmatrix.sync.aligned.m8n8.x4.shared.b16 {%0,%1,%2,%3}, [%4];"
                 : "=r"(r0), "=r"(r1), "=r"(r2), "=r"(r3) : "r"(saddr));
}

// bf16 inputs, fp32 accumulate (proj)
__device__ __forceinline__ void mma16816(float acc[4], uint32_t a0, uint32_t a1,
                                         uint32_t a2, uint32_t a3,
                                         uint32_t b0, uint32_t b1)
{
    asm volatile(
        "mma.sync.aligned.m16n8k16.row.col.f32.bf16.bf16.f32 "
        "{%0,%1,%2,%3}, {%4,%5,%6,%7}, {%8,%9}, {%0,%1,%2,%3};\n"
        : "+f"(acc[0]), "+f"(acc[1]), "+f"(acc[2]), "+f"(acc[3])
        : "r"(a0), "r"(a1), "r"(a2), "r"(a3), "r"(b0), "r"(b1));
}

// e4m3 inputs, fp32 accumulate, K=32 per issue (logits)
__device__ __forceinline__ void mma16832q(float acc[4], uint32_t a0, uint32_t a1,
                                          uint32_t a2, uint32_t a3,
                                          uint32_t b0, uint32_t b1)
{
    asm volatile(
        "mma.sync.aligned.m16n8k32.row.col.f32.e4m3.e4m3.f32 "
        "{%0,%1,%2,%3}, {%4,%5,%6,%7}, {%8,%9}, {%0,%1,%2,%3};\n"
        : "+f"(acc[0]), "+f"(acc[1]), "+f"(acc[2]), "+f"(acc[3])
        : "r"(a0), "r"(a1), "r"(a2), "r"(a3), "r"(b0), "r"(b1));
}

__device__ __forceinline__ float fsqrt_approx(float x) {
    float y;
    asm("sqrt.approx.f32 %0, %1;" : "=f"(y) : "f"(x));
    return y;
}
__device__ __forceinline__ float frcp_approx(float x) {
    float y;
    asm("rcp.approx.f32 %0, %1;" : "=f"(y) : "f"(x));
    return y;
}

__device__ __forceinline__ uint16_t pack_fp8x2(float a, float b) {
    __nv_fp8x2_e4m3 q(make_float2(a, b));
    return *(uint16_t*)&q;
}

// ---------------------------------------------------------------------------
// Proj: xq = fp8(expmap0(features @ W^T + b) * 16). W resident in smem (bf16).
// ---------------------------------------------------------------------------
__global__ __launch_bounds__(512, 1)
void proj_expmap_kernel(const float* __restrict__ A,
                        const float* __restrict__ W,
                        const float* __restrict__ bias,
                        uint8_t* __restrict__ Xq,
                        float* __restrict__ xsq_out)
{
    extern __shared__ __nv_bfloat16 dsm[];
    const uint32_t wbase = smem_u32(dsm);
    const uint32_t abase = wbase + 8u * W_CHUNK_H * 2u;
    __shared__ float rowsum[PM];
    __shared__ float rowscale[PM];

    const int tid = threadIdx.x;
    const int m0  = blockIdx.x * PM;
    if (tid < PM) rowsum[tid] = 0.f;

    const int warp = tid >> 5;
    const int lane = tid & 31;
    const int wm = (warp & 3) * 32;
    const int wn = (warp >> 2) * 64;
    const int g  = lane >> 2;
    const int tg = lane & 3;
    const int lrow16 = lane & 15;
    const int khalf  = (lane >> 4) << 3;

    #pragma unroll
    for (int it = 0; it < 32; it++) {
        int idx = tid + it * 512;
        int r = idx >> 6;
        int c4 = (idx & 63) * 4;
        float4 v = *(const float4*)&W[(size_t)r * DIM + c4];
        __nv_bfloat162 lo = __floats2bfloat162_rn(v.x, v.y);
        __nv_bfloat162 hi = __floats2bfloat162_rn(v.z, v.w);
        uint2 pk; pk.x = *(uint32_t*)&lo; pk.y = *(uint32_t*)&hi;
        int chunk = c4 >> 5;
        int cc = c4 & 31;
        *(uint2*)(dsm + (size_t)(chunk * 256 + r) * LDT + cc) = pk;
    }

    float4 apf[2];
    {
        #pragma unroll
        for (int r = 0; r < 2; r++) {
            int idx = tid + r * 512;
            int row = idx >> 3;
            int cc = (idx & 7) * 4;
            apf[r] = *(const float4*)&A[(size_t)(m0 + row) * DIM + 0 + cc];
        }
    }
    __syncthreads();

    float acc[2][8][4];
    #pragma unroll
    for (int i = 0; i < 2; i++)
        #pragma unroll
        for (int j = 0; j < 8; j++)
            #pragma unroll
            for (int e = 0; e < 4; e++) acc[i][j][e] = 0.f;

    for (int kt = 0; kt < 8; kt++) {
        const uint32_t ast = abase + (uint32_t)((kt & 1) * A_STG_H) * 2u;
        #pragma unroll
        for (int r = 0; r < 2; r++) {
            int idx = tid + r * 512;
            int row = idx >> 3;
            int cc = (idx & 7) * 4;
            __nv_bfloat162 lo = __floats2bfloat162_rn(apf[r].x, apf[r].y);
            __nv_bfloat162 hi = __floats2bfloat162_rn(apf[r].z, apf[r].w);
            uint2 pk; pk.x = *(uint32_t*)&lo; pk.y = *(uint32_t*)&hi;
            *(uint2*)(dsm + (size_t)(8 * W_CHUNK_H) + (size_t)((kt & 1) * PM + row) * LDT + cc) = pk;
        }
        __syncthreads();

        if (kt < 7) {
            const int k0 = (kt + 1) * BK;
            #pragma unroll
            for (int r = 0; r < 2; r++) {
                int idx = tid + r * 512;
                int row = idx >> 3;
                int cc = (idx & 7) * 4;
                apf[r] = *(const float4*)&A[(size_t)(m0 + row) * DIM + k0 + cc];
            }
        }

        const uint32_t bb = wbase + (uint32_t)(kt * W_CHUNK_H) * 2u;
        #pragma unroll
        for (int ks = 0; ks < 2; ks++) {
            const int kc = ks * 16 + khalf;
            uint32_t a[2][4];
            #pragma unroll
            for (int i = 0; i < 2; i++)
                ldm_x4(a[i][0], a[i][1], a[i][2], a[i][3],
                       ast + (uint32_t)((wm + i * 16 + lrow16) * LDT + kc) * 2u);
            #pragma unroll
            for (int jj = 0; jj < 4; jj++) {
                uint32_t b0, b1, b2, b3;
                ldm_x4(b0, b1, b2, b3,
                       bb + (uint32_t)((wn + jj * 16 + lrow16) * LDT + kc) * 2u);
                #pragma unroll
                for (int i = 0; i < 2; i++) {
                    mma16816(acc[i][2 * jj + 0], a[i][0], a[i][1], a[i][2], a[i][3], b0, b2);
                    mma16816(acc[i][2 * jj + 1], a[i][0], a[i][1], a[i][2], a[i][3], b1, b3);
                }
            }
        }
        __syncthreads();
    }

    float part[2][2] = {{0.f, 0.f}, {0.f, 0.f}};
    #pragma unroll
    for (int j = 0; j < 8; j++) {
        const int nb = wn + j * 8 + tg * 2;
        const float b0 = bias[nb], b1 = bias[nb + 1];
        #pragma unroll
        for (int i = 0; i < 2; i++) {
            #pragma unroll
            for (int h = 0; h < 2; h++) {
                float y0 = acc[i][j][2 * h + 0] + b0;
                float y1 = acc[i][j][2 * h + 1] + b1;
                acc[i][j][2 * h + 0] = y0;
                acc[i][j][2 * h + 1] = y1;
                part[i][h] += y0 * y0 + y1 * y1;
            }
        }
    }
    #pragma unroll
    for (int i = 0; i < 2; i++)
        #pragma unroll
        for (int h = 0; h < 2; h++)
            atomicAdd(&rowsum[wm + i * 16 + g + h * 8], part[i][h]);
    __syncthreads();

    if (tid < PM) {
        const float total = rowsum[tid];
        const float norm  = sqrtf(total);
        const float cn    = fmaxf(norm, EPS_F);
        const float s     = tanhf(cn) / cn;
        rowscale[tid] = s * XSCALE;
        xsq_out[m0 + tid] = s * s * total;
    }
    __syncthreads();

    #pragma unroll
    for (int i = 0; i < 2; i++) {
        #pragma unroll
        for (int h = 0; h < 2; h++) {
            const int ml = wm + i * 16 + g + h * 8;
            const float s = rowscale[ml];
            const int m = m0 + ml;
            #pragma unroll
            for (int j = 0; j < 8; j++) {
                const int nb = wn + j * 8 + tg * 2;
                uint16_t q = pack_fp8x2(s * acc[i][j][2 * h + 0],
                                        s * acc[i][j][2 * h + 1]);
                *(uint16_t*)&Xq[(size_t)m * DIM + nb] = q;
            }
        }
    }
}

// ---------------------------------------------------------------------------
// expmap0 for embeddings (fp32 -> e4m3 x16 + ||p||^2)
// ---------------------------------------------------------------------------
__global__ void expmap_kernel(const float* __restrict__ src,
                              uint8_t* __restrict__ dst,
                              float* __restrict__ sq_out)
{
    const int row = blockIdx.x;
    const int tid = threadIdx.x;       // 128 threads, 2 elems each
    const float v0 = src[(size_t)row * DIM + tid * 2 + 0];
    const float v1 = src[(size_t)row * DIM + tid * 2 + 1];

    float s = v0 * v0 + v1 * v1;
    #pragma unroll
    for (int off = 16; off > 0; off >>= 1)
        s += __shfl_xor_sync(0xFFFFFFFFu, s, off);

    __shared__ float warp_s[4];
    __shared__ float total_sh;
    const int warp = tid >> 5;
    if ((tid & 31) == 0) warp_s[warp] = s;
    __syncthreads();
    if (tid == 0) {
        float t = 0.f;
        #pragma unroll
        for (int w = 0; w < 4; w++) t += warp_s[w];
        total_sh = t;
    }
    __syncthreads();

    const float total = total_sh;
    const float norm  = sqrtf(total);
    const float cn    = fmaxf(norm, EPS_F);
    const float scale = tanhf(cn) / cn;

    uint16_t q = pack_fp8x2(scale * XSCALE * v0, scale * XSCALE * v1);
    *(uint16_t*)&dst[(size_t)row * DIM + tid * 2] = q;
    if (tid == 0) sq_out[row] = scale * scale * total;
}

// ---------------------------------------------------------------------------
// Logits GEMM: fp8 e4m3 m16n8k32, 2-stage BK=128 pipeline, fp32 acc,
// approx Poincare epilogue with hoisted reciprocals.
// ---------------------------------------------------------------------------
__global__ __launch_bounds__(256, 2)
void logits_mma_kernel(const uint8_t* __restrict__ Xq,
                       const uint8_t* __restrict__ Pq,
                       const float* __restrict__ xsq,
                       const float* __restrict__ psq,
                       const float* __restrict__ logit_scale,
                       float* __restrict__ Out)
{
    extern __shared__ uint8_t qsm[];
    const uint32_t base = smem_u32(qsm);
    // layout: A stage0, A stage1, B stage0, B stage1
    const uint32_t boff0 = 2u * Q_STG_BYTES;

    const int tid  = threadIdx.x;
    const int m0 = blockIdx.y * BM;
    const int n0 = blockIdx.x * BN;

    const int warp = tid >> 5;
    const int lane = tid & 31;
    const int wm = (warp & 3) * 32;
    const int wn = (warp >> 2) * 64;
    const int g  = lane >> 2;
    const int tg = lane & 3;
    const int lrow16 = lane & 15;
    const int khalf  = (lane >> 4) << 3;   // b16 units

    // stage loader: 1024 x 16B chunks per operand, 4/thread/operand
    auto load_stage = [&](int st) {
        const int k0 = st * BKQ;           // byte offset within 256B row
        const uint32_t soff = (uint32_t)st * Q_STG_BYTES;
        #pragma unroll
        for (int r = 0; r < 4; r++) {
            int idx = tid + r * 256;
            int row = idx >> 3;
            int cb  = (idx & 7) * 16;      // byte offset within 128B stage row
            uint32_t d = soff + (uint32_t)(row * Q_ROW_B + cb);
            cp16s(base + d, &Xq[(size_t)(m0 + row) * DIM + k0 + cb], true);
            cp16s(base + boff0 + d,
                  &Pq[(size_t)(n0 + row) * DIM + k0 + cb], (n0 + row) < NCLS);
        }
        CP_COMMIT();
    };

    load_stage(0);
    load_stage(1);

    float acc[2][8][4];
    #pragma unroll
    for (int i = 0; i < 2; i++)
        #pragma unroll
        for (int j = 0; j < 8; j++)
            #pragma unroll
            for (int e = 0; e < 4; e++) acc[i][j][e] = 0.f;

    #pragma unroll
    for (int st = 0; st < 2; st++) {
        if (st == 0)
            asm volatile("cp.async.wait_group 1;\n" ::: "memory");
        else
            asm volatile("cp.async.wait_group 0;\n" ::: "memory");
        __syncthreads();

        const uint32_t ab = base + (uint32_t)st * Q_STG_BYTES;
        const uint32_t bb = base + boff0 + (uint32_t)st * Q_STG_BYTES;

        // 4 k32 steps per stage
        #pragma unroll
        for (int ks = 0; ks < 4; ks++) {
            const int kc = ks * 16 + khalf;    // b16 col within stage row
            uint32_t a[2][4];
            #pragma unroll
            for (int i = 0; i < 2; i++)
                ldm_x4(a[i][0], a[i][1], a[i][2], a[i][3],
                       ab + (uint32_t)((wm + i * 16 + lrow16) * LDTQ + kc) * 2u);
            #pragma unroll
            for (int jj = 0; jj < 4; jj++) {
                uint32_t b0, b1, b2, b3;
                ldm_x4(b0, b1, b2, b3,
                       bb + (uint32_t)((wn + jj * 16 + lrow16) * LDTQ + kc) * 2u);
                #pragma unroll
                for (int i = 0; i < 2; i++) {
                    mma16832q(acc[i][2 * jj + 0], a[i][0], a[i][1], a[i][2], a[i][3], b0, b2);
                    mma16832q(acc[i][2 * jj + 1], a[i][0], a[i][1], a[i][2], a[i][3], b1, b3);
                }
            }
        }
    }

    // ---- Poincare epilogue (approx MUFU math, hoisted reciprocals)
    const float lscale = fminf(expf(logit_scale[0]), 100.f);

    // per-thread row data: 4 distinct m rows
    float xs[2][2], rx[2][2];
    #pragma unroll
    for (int i = 0; i < 2; i++)
        #pragma unroll
        for (int h = 0; h < 2; h++) {
            const int m = m0 + wm + i * 16 + g + h * 8;
            xs[i][h] = xsq[m];
            rx[i][h] = frcp_approx(fmaxf(1.f - xs[i][h], 0.f)); // +inf ok
        }

    #pragma unroll
    for (int j = 0; j < 8; j++) {
        const int nb = n0 + wn + j * 8 + tg * 2;
        if (nb >= NCLS) continue;              // NCLS even -> pairs in/out together
        const float ps0 = psq[nb], ps1 = psq[nb + 1];
        const float rp0 = frcp_approx(fmaxf(1.f - ps0, 0.f));
        const float rp1 = frcp_approx(fmaxf(1.f - ps1, 0.f));
        #pragma unroll
        for (int i = 0; i < 2; i++) {
            #pragma unroll
            for (int h = 0; h < 2; h++) {
                const int m = m0 + wm + i * 16 + g + h * 8;
                const float xsv = xs[i][h];
                const float rxv = rx[i][h];

                const float xp0 = acc[i][j][2 * h + 0] * INV_XSCALE2;
                const float xp1 = acc[i][j][2 * h + 1] * INV_XSCALE2;
                float d0 = fmaxf(xsv + ps0 - 2.f * xp0, 0.f);
                float d1 = fmaxf(xsv + ps1 - 2.f * xp1, 0.f);
                // 1/max(omx*omp, eps) == min(rcp(omx)*rcp(omp), 1/eps)
                float rr0 = fminf(rxv * rp0, INV_EPS);
                float rr1 = fminf(rxv * rp1, INV_EPS);
                float a0 = fmaxf(fmaf(2.f * d0, rr0, 1.f), 1.f + EPS_F);
                float a1 = fmaxf(fmaf(2.f * d1, rr1, 1.f), 1.f + EPS_F);
                float r0 = __logf(a0 + fsqrt_approx(fmaf(a0, a0, -1.f)));
                float r1 = __logf(a1 + fsqrt_approx(fmaf(a1, a1, -1.f)));
                float2 v = make_float2(-r0 * lscale, -r1 * lscale);
                *(float2*)&Out[(size_t)m * NCLS + nb] = v;
            }
        }
    }
}

// ---------------------------------------------------------------------------
// Launch
// ---------------------------------------------------------------------------
extern "C" void kernel_launch(void* const* d_in, const int* in_sizes, int n_in,
                              void* d_out, int out_size)
{
    const float* features    = (const float*)d_in[0];
    const float* W           = (const float*)d_in[1];
    const float* bias        = (const float*)d_in[2];
    const float* embeddings  = (const float*)d_in[3];
    const float* logit_scale = (const float*)d_in[4];
    float* out = (float*)d_out;

    uint8_t *xq, *pq;
    float *xsq, *psq;
    cudaGetSymbolAddress((void**)&xq,  g_xq);
    cudaGetSymbolAddress((void**)&xsq, g_xsq);
    cudaGetSymbolAddress((void**)&pq,  g_pq);
    cudaGetSymbolAddress((void**)&psq, g_psq);

    // 1. Fused proj (W-resident smem) + expmap -> xq (fp8 x16), xsq
    cudaFuncSetAttribute(proj_expmap_kernel,
                         cudaFuncAttributeMaxDynamicSharedMemorySize, PROJ_SMEM);
    proj_expmap_kernel<<<MROWS / PM, 512, PROJ_SMEM>>>(features, W, bias, xq, xsq);

    // 2. expmap0 on embeddings -> pq (fp8 x16), psq
    expmap_kernel<<<NCLS, 128>>>(embeddings, pq, psq);

    // 3. Logits GEMM (fp8 m16n8k32, 2-stage pipeline) + approx Poincare epilogue
    cudaFuncSetAttribute(logits_mma_kernel,
                         cudaFuncAttributeMaxDynamicSharedMemorySize, LOGITS_SMEM);
    {
        dim3 grid((NCLS + BN - 1) / BN, MROWS / BM);   // (8, 256)
        logits_mma_kernel<<<grid, 256, LOGITS_SMEM>>>(xq, pq, xsq, psq,
                                                      logit_scale, out);
    }
}

// round 16
// speedup vs baseline: 1.1151x; 1.1007x over previous
#include <cuda_runtime.h>
#include <cuda_bf16.h>
#include <cuda_fp16.h>
#include <math.h>
#include <stdint.h>

// Problem constants
#define BATCH   4
#define SEQ     8192
#define MROWS   (BATCH * SEQ)   // 32768
#define DIM     256
#define NCLS    1000
#define EPS_F   1e-5f
#define INV_EPS 1e5f

#define BK  32
#define LDT 40                  // proj: 80B padded row

// Proj: CTA 128x256, 16 warps (4M x 4N), warp 32x64. W resident in smem.
#define PM 128
#define W_CHUNK_H (256 * LDT)
#define A_STG_H   (PM * LDT)
#define PROJ_SMEM ((8 * W_CHUNK_H + 2 * A_STG_H) * 2)   // 184320 B

// Logits: 128x128 CTA, 8 warps (4M x 2N), warp 32x64, BK=64, 2-stage, fp16
#define BM 128
#define BN 128
#define BKL 64
#define LDTL 72                                // 144B row stride, ldmatrix-clean
#define LSTG_BYTES (BM * LDTL * 2)             // 18432 B per operand-stage
#define LOGITS_SMEM (4 * LSTG_BYTES)           // 73728 B (x3 CTA = 216KB/SM)

// Scratch
__device__ __half g_xh[MROWS * DIM];          // expmapped features (fp16)
__device__ float  g_xsq[MROWS];
__device__ __half g_ph[NCLS * DIM];           // expmapped prototypes (fp16)
__device__ float  g_psq[NCLS];

// ---------------------------------------------------------------------------
// PTX helpers (base-sm_103-legal only)
// ---------------------------------------------------------------------------
__device__ __forceinline__ uint32_t smem_u32(const void* p) {
    return (uint32_t)__cvta_generic_to_shared(p);
}
__device__ __forceinline__ void cp16s(uint32_t dst_saddr, const void* src, bool valid)
{
    int sz = valid ? 16 : 0;
    asm volatile("cp.async.cg.shared.global [%0], [%1], 16, %2;\n"
                 :: "r"(dst_saddr), "l"(src), "r"(sz));
}
#define CP_COMMIT() asm volatile("cp.async.commit_group;\n" ::: "memory")

__device__ __forceinline__ void ldm_x4(uint32_t& r0, uint32_t& r1,
                                       uint32_t& r2, uint32_t& r3, uint32_t saddr)
{
    asm volatile("ldmatrix.sync.aligned.m8n8.x4.shared.b16 {%0,%1,%2,%3}, [%4];"
                 : "=r"(r0), "=r"(r1), "=r"(r2), "=r"(r3) : "r"(saddr));
}

// bf16 inputs, fp32 accumulate (proj)
__device__ __forceinline__ void mma16816(float acc[4], uint32_t a0, uint32_t a1,
                                         uint32_t a2, uint32_t a3,
                                         uint32_t b0, uint32_t b1)
{
    asm volatile(
        "mma.sync.aligned.m16n8k16.row.col.f32.bf16.bf16.f32 "
        "{%0,%1,%2,%3}, {%4,%5,%6,%7}, {%8,%9}, {%0,%1,%2,%3};\n"
        : "+f"(acc[0]), "+f"(acc[1]), "+f"(acc[2]), "+f"(acc[3])
        : "r"(a0), "r"(a1), "r"(a2), "r"(a3), "r"(b0), "r"(b1));
}

// fp16 inputs, fp16 accumulate (logits) — halves accumulator registers
__device__ __forceinline__ void mma16816h(uint32_t& c0, uint32_t& c1,
                                          uint32_t a0, uint32_t a1,
                                          uint32_t a2, uint32_t a3,
                                          uint32_t b0, uint32_t b1)
{
    asm volatile(
        "mma.sync.aligned.m16n8k16.row.col.f16.f16.f16.f16 "
        "{%0,%1}, {%2,%3,%4,%5}, {%6,%7}, {%0,%1};\n"
        : "+r"(c0), "+r"(c1)
        : "r"(a0), "r"(a1), "r"(a2), "r"(a3), "r"(b0), "r"(b1));
}

__device__ __forceinline__ float fsqrt_approx(float x) {
    float y;
    asm("sqrt.approx.f32 %0, %1;" : "=f"(y) : "f"(x));
    return y;
}
__device__ __forceinline__ float frcp_approx(float x) {
    float y;
    asm("rcp.approx.f32 %0, %1;" : "=f"(y) : "f"(x));
    return y;
}

// ---------------------------------------------------------------------------
// Proj: xh = expmap0(features @ W^T + b). W resident in smem (bf16), fp32 acc.
// (unchanged round-10/12 winner)
// ---------------------------------------------------------------------------
__global__ __launch_bounds__(512, 1)
void proj_expmap_kernel(const float* __restrict__ A,
                        const float* __restrict__ W,
                        const float* __restrict__ bias,
                        __half* __restrict__ Xh,
                        float* __restrict__ xsq_out)
{
    extern __shared__ __nv_bfloat16 dsm[];
    const uint32_t wbase = smem_u32(dsm);
    const uint32_t abase = wbase + 8u * W_CHUNK_H * 2u;
    __shared__ float rowsum[PM];
    __shared__ float rowscale[PM];

    const int tid = threadIdx.x;
    const int m0  = blockIdx.x * PM;
    if (tid < PM) rowsum[tid] = 0.f;

    const int warp = tid >> 5;
    const int lane = tid & 31;
    const int wm = (warp & 3) * 32;
    const int wn = (warp >> 2) * 64;
    const int g  = lane >> 2;
    const int tg = lane & 3;
    const int lrow16 = lane & 15;
    const int khalf  = (lane >> 4) << 3;

    #pragma unroll
    for (int it = 0; it < 32; it++) {
        int idx = tid + it * 512;
        int r = idx >> 6;
        int c4 = (idx & 63) * 4;
        float4 v = *(const float4*)&W[(size_t)r * DIM + c4];
        __nv_bfloat162 lo = __floats2bfloat162_rn(v.x, v.y);
        __nv_bfloat162 hi = __floats2bfloat162_rn(v.z, v.w);
        uint2 pk; pk.x = *(uint32_t*)&lo; pk.y = *(uint32_t*)&hi;
        int chunk = c4 >> 5;
        int cc = c4 & 31;
        *(uint2*)(dsm + (size_t)(chunk * 256 + r) * LDT + cc) = pk;
    }

    float4 apf[2];
    {
        #pragma unroll
        for (int r = 0; r < 2; r++) {
            int idx = tid + r * 512;
            int row = idx >> 3;
            int cc = (idx & 7) * 4;
            apf[r] = *(const float4*)&A[(size_t)(m0 + row) * DIM + 0 + cc];
        }
    }
    __syncthreads();

    float acc[2][8][4];
    #pragma unroll
    for (int i = 0; i < 2; i++)
        #pragma unroll
        for (int j = 0; j < 8; j++)
            #pragma unroll
            for (int e = 0; e < 4; e++) acc[i][j][e] = 0.f;

    for (int kt = 0; kt < 8; kt++) {
        const uint32_t ast = abase + (uint32_t)((kt & 1) * A_STG_H) * 2u;
        #pragma unroll
        for (int r = 0; r < 2; r++) {
            int idx = tid + r * 512;
            int row = idx >> 3;
            int cc = (idx & 7) * 4;
            __nv_bfloat162 lo = __floats2bfloat162_rn(apf[r].x, apf[r].y);
            __nv_bfloat162 hi = __floats2bfloat162_rn(apf[r].z, apf[r].w);
            uint2 pk; pk.x = *(uint32_t*)&lo; pk.y = *(uint32_t*)&hi;
            *(uint2*)(dsm + (size_t)(8 * W_CHUNK_H) + (size_t)((kt & 1) * PM + row) * LDT + cc) = pk;
        }
        __syncthreads();

        if (kt < 7) {
            const int k0 = (kt + 1) * BK;
            #pragma unroll
            for (int r = 0; r < 2; r++) {
                int idx = tid + r * 512;
                int row = idx >> 3;
                int cc = (idx & 7) * 4;
                apf[r] = *(const float4*)&A[(size_t)(m0 + row) * DIM + k0 + cc];
            }
        }

        const uint32_t bb = wbase + (uint32_t)(kt * W_CHUNK_H) * 2u;
        #pragma unroll
        for (int ks = 0; ks < 2; ks++) {
            const int kc = ks * 16 + khalf;
            uint32_t a[2][4];
            #pragma unroll
            for (int i = 0; i < 2; i++)
                ldm_x4(a[i][0], a[i][1], a[i][2], a[i][3],
                       ast + (uint32_t)((wm + i * 16 + lrow16) * LDT + kc) * 2u);
            #pragma unroll
            for (int jj = 0; jj < 4; jj++) {
                uint32_t b0, b1, b2, b3;
                ldm_x4(b0, b1, b2, b3,
                       bb + (uint32_t)((wn + jj * 16 + lrow16) * LDT + kc) * 2u);
                #pragma unroll
                for (int i = 0; i < 2; i++) {
                    mma16816(acc[i][2 * jj + 0], a[i][0], a[i][1], a[i][2], a[i][3], b0, b2);
                    mma16816(acc[i][2 * jj + 1], a[i][0], a[i][1], a[i][2], a[i][3], b1, b3);
                }
            }
        }
        __syncthreads();
    }

    float part[2][2] = {{0.f, 0.f}, {0.f, 0.f}};
    #pragma unroll
    for (int j = 0; j < 8; j++) {
        const int nb = wn + j * 8 + tg * 2;
        const float b0 = bias[nb], b1 = bias[nb + 1];
        #pragma unroll
        for (int i = 0; i < 2; i++) {
            #pragma unroll
            for (int h = 0; h < 2; h++) {
                float y0 = acc[i][j][2 * h + 0] + b0;
                float y1 = acc[i][j][2 * h + 1] + b1;
                acc[i][j][2 * h + 0] = y0;
                acc[i][j][2 * h + 1] = y1;
                part[i][h] += y0 * y0 + y1 * y1;
            }
        }
    }
    #pragma unroll
    for (int i = 0; i < 2; i++)
        #pragma unroll
        for (int h = 0; h < 2; h++)
            atomicAdd(&rowsum[wm + i * 16 + g + h * 8], part[i][h]);
    __syncthreads();

    if (tid < PM) {
        const float total = rowsum[tid];
        const float norm  = sqrtf(total);
        const float cn    = fmaxf(norm, EPS_F);
        const float s     = tanhf(cn) / cn;
        rowscale[tid] = s;
        xsq_out[m0 + tid] = s * s * total;
    }
    __syncthreads();

    #pragma unroll
    for (int i = 0; i < 2; i++) {
        #pragma unroll
        for (int h = 0; h < 2; h++) {
            const int ml = wm + i * 16 + g + h * 8;
            const float s = rowscale[ml];
            const int m = m0 + ml;
            #pragma unroll
            for (int j = 0; j < 8; j++) {
                const int nb = wn + j * 8 + tg * 2;
                __half2 v = __floats2half2_rn(
                    s * acc[i][j][2 * h + 0], s * acc[i][j][2 * h + 1]);
                *(__half2*)&Xh[(size_t)m * DIM + nb] = v;
            }
        }
    }
}

// ---------------------------------------------------------------------------
// expmap0 for embeddings: warp-per-row (no block barriers), 8 rows / block
// ---------------------------------------------------------------------------
__global__ __launch_bounds__(256)
void expmap_kernel(const float* __restrict__ src,
                   __half* __restrict__ dst,
                   float* __restrict__ sq_out)
{
    const int warp = threadIdx.x >> 5;
    const int lane = threadIdx.x & 31;
    const int row  = blockIdx.x * 8 + warp;
    if (row >= NCLS) return;

    // each lane: 8 consecutive elements (two float4)
    float4 v0 = *(const float4*)&src[(size_t)row * DIM + lane * 8 + 0];
    float4 v1 = *(const float4*)&src[(size_t)row * DIM + lane * 8 + 4];

    float s = v0.x * v0.x + v0.y * v0.y + v0.z * v0.z + v0.w * v0.w
            + v1.x * v1.x + v1.y * v1.y + v1.z * v1.z + v1.w * v1.w;
    #pragma unroll
    for (int off = 16; off > 0; off >>= 1)
        s += __shfl_xor_sync(0xFFFFFFFFu, s, off);

    const float total = s;
    const float norm  = sqrtf(total);
    const float cn    = fmaxf(norm, EPS_F);
    const float scale = tanhf(cn) / cn;

    __half2 o[4];
    o[0] = __floats2half2_rn(scale * v0.x, scale * v0.y);
    o[1] = __floats2half2_rn(scale * v0.z, scale * v0.w);
    o[2] = __floats2half2_rn(scale * v1.x, scale * v1.y);
    o[3] = __floats2half2_rn(scale * v1.z, scale * v1.w);
    *(uint4*)&dst[(size_t)row * DIM + lane * 8] = *(uint4*)o;

    if (lane == 0) sq_out[row] = scale * scale * total;
}

// ---------------------------------------------------------------------------
// Logits GEMM: fp16 in / fp16 acc, BK=64 2-stage, 3 CTAs/SM target,
// approx Poincare epilogue with hoisted reciprocals.
// ---------------------------------------------------------------------------
__global__ __launch_bounds__(256, 3)
void logits_mma_kernel(const __half* __restrict__ Xh,
                       const __half* __restrict__ Ph,
                       const float* __restrict__ xsq,
                       const float* __restrict__ psq,
                       const float* __restrict__ logit_scale,
                       float* __restrict__ Out)
{
    extern __shared__ __half hsm[];
    const uint32_t base = smem_u32(hsm);
    const uint32_t boff0 = 2u * LSTG_BYTES;

    const int tid  = threadIdx.x;
    const int m0 = blockIdx.y * BM;
    const int n0 = blockIdx.x * BN;

    const int warp = tid >> 5;
    const int lane = tid & 31;
    const int wm = (warp & 3) * 32;
    const int wn = (warp >> 2) * 64;
    const int g  = lane >> 2;
    const int tg = lane & 3;
    const int lrow16 = lane & 15;
    const int khalf  = (lane >> 4) << 3;

    // fp16 accumulators: [i][j][h] = half2 {col nb, col nb+1} for row g + 8h
    uint32_t acc[2][8][2];
    #pragma unroll
    for (int i = 0; i < 2; i++)
        #pragma unroll
        for (int j = 0; j < 8; j++) {
            acc[i][j][0] = 0u;
            acc[i][j][1] = 0u;
        }

    const int NKT = DIM / BKL;   // 4

    auto load_stage = [&](int kt, int st) {
        const int k0 = kt * BKL;
        const uint32_t soff = (uint32_t)st * LSTG_BYTES;
        #pragma unroll
        for (int r = 0; r < 4; r++) {
            int idx = tid + r * 256;
            int row = idx >> 3;
            int ch  = (idx & 7) * 8;
            uint32_t d = soff + (uint32_t)(row * LDTL + ch) * 2u;
            cp16s(base + d, &Xh[(size_t)(m0 + row) * DIM + k0 + ch], true);
            cp16s(base + boff0 + d,
                  &Ph[(size_t)(n0 + row) * DIM + k0 + ch], (n0 + row) < NCLS);
        }
        CP_COMMIT();
    };

    load_stage(0, 0);
    load_stage(1, 1);

    for (int kt = 0; kt < NKT; kt++) {
        if (kt < NKT - 1)
            asm volatile("cp.async.wait_group 1;\n" ::: "memory");
        else
            asm volatile("cp.async.wait_group 0;\n" ::: "memory");
        __syncthreads();

        const int st = kt & 1;
        const uint32_t ab = base + (uint32_t)st * LSTG_BYTES;
        const uint32_t bb = base + boff0 + (uint32_t)st * LSTG_BYTES;

        #pragma unroll
        for (int ks = 0; ks < 4; ks++) {
            const int kc = ks * 16 + khalf;
            uint32_t a[2][4];
            #pragma unroll
            for (int i = 0; i < 2; i++)
                ldm_x4(a[i][0], a[i][1], a[i][2], a[i][3],
                       ab + (uint32_t)((wm + i * 16 + lrow16) * LDTL + kc) * 2u);
            #pragma unroll
            for (int jj = 0; jj < 4; jj++) {
                uint32_t b0, b1, b2, b3;
                ldm_x4(b0, b1, b2, b3,
                       bb + (uint32_t)((wn + jj * 16 + lrow16) * LDTL + kc) * 2u);
                #pragma unroll
                for (int i = 0; i < 2; i++) {
                    mma16816h(acc[i][2 * jj + 0][0], acc[i][2 * jj + 0][1],
                              a[i][0], a[i][1], a[i][2], a[i][3], b0, b2);
                    mma16816h(acc[i][2 * jj + 1][0], acc[i][2 * jj + 1][1],
                              a[i][0], a[i][1], a[i][2], a[i][3], b1, b3);
                }
            }
        }
        __syncthreads();
        if (kt + 2 < NKT) load_stage(kt + 2, st);
    }

    // ---- Poincare epilogue (approx MUFU math, hoisted reciprocals)
    const float lscale = fminf(expf(logit_scale[0]), 100.f);

    float xs[2][2], rx[2][2];
    #pragma unroll
    for (int i = 0; i < 2; i++)
        #pragma unroll
        for (int h = 0; h < 2; h++) {
            const int m = m0 + wm + i * 16 + g + h * 8;
            xs[i][h] = xsq[m];
            rx[i][h] = frcp_approx(fmaxf(1.f - xs[i][h], 0.f));  // +inf ok
        }

    #pragma unroll
    for (int j = 0; j < 8; j++) {
        const int nb = n0 + wn + j * 8 + tg * 2;
        if (nb >= NCLS) continue;              // NCLS even -> pairs in/out together
        const float ps0 = psq[nb], ps1 = psq[nb + 1];
        const float rp0 = frcp_approx(fmaxf(1.f - ps0, 0.f));
        const float rp1 = frcp_approx(fmaxf(1.f - ps1, 0.f));
        #pragma unroll
        for (int i = 0; i < 2; i++) {
            #pragma unroll
            for (int h = 0; h < 2; h++) {
                const int m = m0 + wm + i * 16 + g + h * 8;
                const float xsv = xs[i][h];
                const float rxv = rx[i][h];

                const float2 xp = __half22float2(*(__half2*)&acc[i][j][h]);
                float d0 = fmaxf(xsv + ps0 - 2.f * xp.x, 0.f);
                float d1 = fmaxf(xsv + ps1 - 2.f * xp.y, 0.f);
                // 1/max(omx*omp, eps) == min(rcp(omx)*rcp(omp), 1/eps)
                float rr0 = fminf(rxv * rp0, INV_EPS);
                float rr1 = fminf(rxv * rp1, INV_EPS);
                float a0 = fmaxf(fmaf(2.f * d0, rr0, 1.f), 1.f + EPS_F);
                float a1 = fmaxf(fmaf(2.f * d1, rr1, 1.f), 1.f + EPS_F);
                float r0 = __logf(a0 + fsqrt_approx(fmaf(a0, a0, -1.f)));
                float r1 = __logf(a1 + fsqrt_approx(fmaf(a1, a1, -1.f)));
                float2 v = make_float2(-r0 * lscale, -r1 * lscale);
                *(float2*)&Out[(size_t)m * NCLS + nb] = v;
            }
        }
    }
}

// ---------------------------------------------------------------------------
// Launch
// ---------------------------------------------------------------------------
extern "C" void kernel_launch(void* const* d_in, const int* in_sizes, int n_in,
                              void* d_out, int out_size)
{
    const float* features    = (const float*)d_in[0];
    const float* W           = (const float*)d_in[1];
    const float* bias        = (const float*)d_in[2];
    const float* embeddings  = (const float*)d_in[3];
    const float* logit_scale = (const float*)d_in[4];
    float* out = (float*)d_out;

    __half *xh, *ph;
    float *xsq, *psq;
    cudaGetSymbolAddress((void**)&xh,  g_xh);
    cudaGetSymbolAddress((void**)&xsq, g_xsq);
    cudaGetSymbolAddress((void**)&ph,  g_ph);
    cudaGetSymbolAddress((void**)&psq, g_psq);

    // 1. Fused proj (W-resident smem, A prefetch) + expmap -> xh, xsq
    cudaFuncSetAttribute(proj_expmap_kernel,
                         cudaFuncAttributeMaxDynamicSharedMemorySize, PROJ_SMEM);
    proj_expmap_kernel<<<MROWS / PM, 512, PROJ_SMEM>>>(features, W, bias, xh, xsq);

    // 2. expmap0 on embeddings (warp-per-row) -> ph, psq
    expmap_kernel<<<(NCLS + 7) / 8, 256>>>(embeddings, ph, psq);

    // 3. Logits GEMM (fp16, BK=64 2-stage, 3 CTA/SM) + approx Poincare epilogue
    cudaFuncSetAttribute(logits_mma_kernel,
                         cudaFuncAttributeMaxDynamicSharedMemorySize, LOGITS_SMEM);
    {
        dim3 grid((NCLS + BN - 1) / BN, MROWS / BM);   // (8, 256)
        logits_mma_kernel<<<grid, 256, LOGITS_SMEM>>>(xh, ph, xsq, psq,
                                                      logit_scale, out);
    }
}

// round 17
// speedup vs baseline: 1.1158x; 1.0006x over previous
#include <cuda_runtime.h>
#include <cuda_bf16.h>
#include <cuda_fp16.h>
#include <math.h>
#include <stdint.h>

// Problem constants
#define BATCH   4
#define SEQ     8192
#define MROWS   (BATCH * SEQ)   // 32768
#define DIM     256
#define NCLS    1000
#define EPS_F   1e-5f
#define INV_EPS 1e5f

#define BK  32
#define LDT 40                  // 80B padded row, ldmatrix-clean

// Proj: CTA 128x256, 16 warps (4M x 4N), warp 32x64. W resident in smem.
#define PM 128
#define W_CHUNK_H (256 * LDT)
#define A_STG_H   (PM * LDT)
#define PROJ_SMEM ((8 * W_CHUNK_H + 2 * A_STG_H) * 2)   // 184320 B

// Logits: 128x128 CTA, 8 warps (4M x 2N), warp 32x64, BK=32, 2-stage, fp16
// 4 CTAs/SM target: smem 40960 B/CTA, 64 regs/thread cap.
#define BM 128
#define BN 128
#define LSTG_BYTES (BM * LDT * 2)              // 10240 B per operand-stage
#define LOGITS_SMEM (4 * LSTG_BYTES)           // 40960 B

// Scratch
__device__ __half g_xh[MROWS * DIM];          // expmapped features (fp16)
__device__ float  g_xsq[MROWS];
__device__ __half g_ph[NCLS * DIM];           // expmapped prototypes (fp16)
__device__ float  g_psq[NCLS];

// ---------------------------------------------------------------------------
// PTX helpers (base-sm_103-legal only)
// ---------------------------------------------------------------------------
__device__ __forceinline__ uint32_t smem_u32(const void* p) {
    return (uint32_t)__cvta_generic_to_shared(p);
}
__device__ __forceinline__ void cp16s(uint32_t dst_saddr, const void* src, bool valid)
{
    int sz = valid ? 16 : 0;
    asm volatile("cp.async.cg.shared.global [%0], [%1], 16, %2;\n"
                 :: "r"(dst_saddr), "l"(src), "r"(sz));
}
#define CP_COMMIT() asm volatile("cp.async.commit_group;\n" ::: "memory")

__device__ __forceinline__ void ldm_x4(uint32_t& r0, uint32_t& r1,
                                       uint32_t& r2, uint32_t& r3, uint32_t saddr)
{
    asm volatile("ldmatrix.sync.aligned.m8n8.x4.shared.b16 {%0,%1,%2,%3}, [%4];"
                 : "=r"(r0), "=r"(r1), "=r"(r2), "=r"(r3) : "r"(saddr));
}

// bf16 inputs, fp32 accumulate (proj)
__device__ __forceinline__ void mma16816(float acc[4], uint32_t a0, uint32_t a1,
                                         uint32_t a2, uint32_t a3,
                                         uint32_t b0, uint32_t b1)
{
    asm volatile(
        "mma.sync.aligned.m16n8k16.row.col.f32.bf16.bf16.f32 "
        "{%0,%1,%2,%3}, {%4,%5,%6,%7}, {%8,%9}, {%0,%1,%2,%3};\n"
        : "+f"(acc[0]), "+f"(acc[1]), "+f"(acc[2]), "+f"(acc[3])
        : "r"(a0), "r"(a1), "r"(a2), "r"(a3), "r"(b0), "r"(b1));
}

// fp16 inputs, fp16 accumulate (logits) — halves accumulator registers
__device__ __forceinline__ void mma16816h(uint32_t& c0, uint32_t& c1,
                                          uint32_t a0, uint32_t a1,
                                          uint32_t a2, uint32_t a3,
                                          uint32_t b0, uint32_t b1)
{
    asm volatile(
        "mma.sync.aligned.m16n8k16.row.col.f16.f16.f16.f16 "
        "{%0,%1}, {%2,%3,%4,%5}, {%6,%7}, {%0,%1};\n"
        : "+r"(c0), "+r"(c1)
        : "r"(a0), "r"(a1), "r"(a2), "r"(a3), "r"(b0), "r"(b1));
}

__device__ __forceinline__ float fsqrt_approx(float x) {
    float y;
    asm("sqrt.approx.f32 %0, %1;" : "=f"(y) : "f"(x));
    return y;
}
__device__ __forceinline__ float frcp_approx(float x) {
    float y;
    asm("rcp.approx.f32 %0, %1;" : "=f"(y) : "f"(x));
    return y;
}

// ---------------------------------------------------------------------------
// Proj: xh = expmap0(features @ W^T + b). W resident in smem (bf16), fp32 acc.
// One barrier per k-iteration (stage-overwrite ordered by the NEXT kt's
// post-STS barrier: MMA(st)@kt < sync@kt+1 < STS(st)@kt+2).
// ---------------------------------------------------------------------------
__global__ __launch_bounds__(512, 1)
void proj_expmap_kernel(const float* __restrict__ A,
                        const float* __restrict__ W,
                        const float* __restrict__ bias,
                        __half* __restrict__ Xh,
                        float* __restrict__ xsq_out)
{
    extern __shared__ __nv_bfloat16 dsm[];
    const uint32_t wbase = smem_u32(dsm);
    const uint32_t abase = wbase + 8u * W_CHUNK_H * 2u;
    __shared__ float rowsum[PM];
    __shared__ float rowscale[PM];

    const int tid = threadIdx.x;
    const int m0  = blockIdx.x * PM;
    if (tid < PM) rowsum[tid] = 0.f;

    const int warp = tid >> 5;
    const int lane = tid & 31;
    const int wm = (warp & 3) * 32;
    const int wn = (warp >> 2) * 64;
    const int g  = lane >> 2;
    const int tg = lane & 3;
    const int lrow16 = lane & 15;
    const int khalf  = (lane >> 4) << 3;

    #pragma unroll
    for (int it = 0; it < 32; it++) {
        int idx = tid + it * 512;
        int r = idx >> 6;
        int c4 = (idx & 63) * 4;
        float4 v = *(const float4*)&W[(size_t)r * DIM + c4];
        __nv_bfloat162 lo = __floats2bfloat162_rn(v.x, v.y);
        __nv_bfloat162 hi = __floats2bfloat162_rn(v.z, v.w);
        uint2 pk; pk.x = *(uint32_t*)&lo; pk.y = *(uint32_t*)&hi;
        int chunk = c4 >> 5;
        int cc = c4 & 31;
        *(uint2*)(dsm + (size_t)(chunk * 256 + r) * LDT + cc) = pk;
    }

    float4 apf[2];
    {
        #pragma unroll
        for (int r = 0; r < 2; r++) {
            int idx = tid + r * 512;
            int row = idx >> 3;
            int cc = (idx & 7) * 4;
            apf[r] = *(const float4*)&A[(size_t)(m0 + row) * DIM + 0 + cc];
        }
    }
    __syncthreads();   // W smem + rowsum init ready

    float acc[2][8][4];
    #pragma unroll
    for (int i = 0; i < 2; i++)
        #pragma unroll
        for (int j = 0; j < 8; j++)
            #pragma unroll
            for (int e = 0; e < 4; e++) acc[i][j][e] = 0.f;

    for (int kt = 0; kt < 8; kt++) {
        const uint32_t ast = abase + (uint32_t)((kt & 1) * A_STG_H) * 2u;
        #pragma unroll
        for (int r = 0; r < 2; r++) {
            int idx = tid + r * 512;
            int row = idx >> 3;
            int cc = (idx & 7) * 4;
            __nv_bfloat162 lo = __floats2bfloat162_rn(apf[r].x, apf[r].y);
            __nv_bfloat162 hi = __floats2bfloat162_rn(apf[r].z, apf[r].w);
            uint2 pk; pk.x = *(uint32_t*)&lo; pk.y = *(uint32_t*)&hi;
            *(uint2*)(dsm + (size_t)(8 * W_CHUNK_H) + (size_t)((kt & 1) * PM + row) * LDT + cc) = pk;
        }
        __syncthreads();   // stage visible; also orders MMA@kt-1 < STS@kt+1

        if (kt < 7) {
            const int k0 = (kt + 1) * BK;
            #pragma unroll
            for (int r = 0; r < 2; r++) {
                int idx = tid + r * 512;
                int row = idx >> 3;
                int cc = (idx & 7) * 4;
                apf[r] = *(const float4*)&A[(size_t)(m0 + row) * DIM + k0 + cc];
            }
        }

        const uint32_t bb = wbase + (uint32_t)(kt * W_CHUNK_H) * 2u;
        #pragma unroll
        for (int ks = 0; ks < 2; ks++) {
            const int kc = ks * 16 + khalf;
            uint32_t a[2][4];
            #pragma unroll
            for (int i = 0; i < 2; i++)
                ldm_x4(a[i][0], a[i][1], a[i][2], a[i][3],
                       ast + (uint32_t)((wm + i * 16 + lrow16) * LDT + kc) * 2u);
            #pragma unroll
            for (int jj = 0; jj < 4; jj++) {
                uint32_t b0, b1, b2, b3;
                ldm_x4(b0, b1, b2, b3,
                       bb + (uint32_t)((wn + jj * 16 + lrow16) * LDT + kc) * 2u);
                #pragma unroll
                for (int i = 0; i < 2; i++) {
                    mma16816(acc[i][2 * jj + 0], a[i][0], a[i][1], a[i][2], a[i][3], b0, b2);
                    mma16816(acc[i][2 * jj + 1], a[i][0], a[i][1], a[i][2], a[i][3], b1, b3);
                }
            }
        }
        // no post-MMA barrier: next iteration's post-STS barrier orders the
        // stage overwrite two iterations out.
    }
    __syncthreads();   // all MMA done before epilogue's atomicAdd/rowsum use

    float part[2][2] = {{0.f, 0.f}, {0.f, 0.f}};
    #pragma unroll
    for (int j = 0; j < 8; j++) {
        const int nb = wn + j * 8 + tg * 2;
        const float b0 = bias[nb], b1 = bias[nb + 1];
        #pragma unroll
        for (int i = 0; i < 2; i++) {
            #pragma unroll
            for (int h = 0; h < 2; h++) {
                float y0 = acc[i][j][2 * h + 0] + b0;
                float y1 = acc[i][j][2 * h + 1] + b1;
                acc[i][j][2 * h + 0] = y0;
                acc[i][j][2 * h + 1] = y1;
                part[i][h] += y0 * y0 + y1 * y1;
            }
        }
    }
    #pragma unroll
    for (int i = 0; i < 2; i++)
        #pragma unroll
        for (int h = 0; h < 2; h++)
            atomicAdd(&rowsum[wm + i * 16 + g + h * 8], part[i][h]);
    __syncthreads();

    if (tid < PM) {
        const float total = rowsum[tid];
        const float norm  = sqrtf(total);
        const float cn    = fmaxf(norm, EPS_F);
        const float s     = tanhf(cn) / cn;
        rowscale[tid] = s;
        xsq_out[m0 + tid] = s * s * total;
    }
    __syncthreads();

    #pragma unroll
    for (int i = 0; i < 2; i++) {
        #pragma unroll
        for (int h = 0; h < 2; h++) {
            const int ml = wm + i * 16 + g + h * 8;
            const float s = rowscale[ml];
            const int m = m0 + ml;
            #pragma unroll
            for (int j = 0; j < 8; j++) {
                const int nb = wn + j * 8 + tg * 2;
                __half2 v = __floats2half2_rn(
                    s * acc[i][j][2 * h + 0], s * acc[i][j][2 * h + 1]);
                *(__half2*)&Xh[(size_t)m * DIM + nb] = v;
            }
        }
    }
}

// ---------------------------------------------------------------------------
// expmap0 for embeddings: warp-per-row, 8 rows / block
// ---------------------------------------------------------------------------
__global__ __launch_bounds__(256)
void expmap_kernel(const float* __restrict__ src,
                   __half* __restrict__ dst,
                   float* __restrict__ sq_out)
{
    const int warp = threadIdx.x >> 5;
    const int lane = threadIdx.x & 31;
    const int row  = blockIdx.x * 8 + warp;
    if (row >= NCLS) return;

    float4 v0 = *(const float4*)&src[(size_t)row * DIM + lane * 8 + 0];
    float4 v1 = *(const float4*)&src[(size_t)row * DIM + lane * 8 + 4];

    float s = v0.x * v0.x + v0.y * v0.y + v0.z * v0.z + v0.w * v0.w
            + v1.x * v1.x + v1.y * v1.y + v1.z * v1.z + v1.w * v1.w;
    #pragma unroll
    for (int off = 16; off > 0; off >>= 1)
        s += __shfl_xor_sync(0xFFFFFFFFu, s, off);

    const float total = s;
    const float norm  = sqrtf(total);
    const float cn    = fmaxf(norm, EPS_F);
    const float scale = tanhf(cn) / cn;

    __half2 o[4];
    o[0] = __floats2half2_rn(scale * v0.x, scale * v0.y);
    o[1] = __floats2half2_rn(scale * v0.z, scale * v0.w);
    o[2] = __floats2half2_rn(scale * v1.x, scale * v1.y);
    o[3] = __floats2half2_rn(scale * v1.z, scale * v1.w);
    *(uint4*)&dst[(size_t)row * DIM + lane * 8] = *(uint4*)o;

    if (lane == 0) sq_out[row] = scale * scale * total;
}

// ---------------------------------------------------------------------------
// Logits GEMM: fp16 in / fp16 acc, BK=32 2-stage, 4 CTAs/SM target,
// approx Poincare epilogue with hoisted reciprocals.
// ---------------------------------------------------------------------------
__global__ __launch_bounds__(256, 4)
void logits_mma_kernel(const __half* __restrict__ Xh,
                       const __half* __restrict__ Ph,
                       const float* __restrict__ xsq,
                       const float* __restrict__ psq,
                       const float* __restrict__ logit_scale,
                       float* __restrict__ Out)
{
    extern __shared__ __half hsm[];
    const uint32_t base = smem_u32(hsm);
    const uint32_t boff0 = 2u * LSTG_BYTES;

    const int tid  = threadIdx.x;
    const int m0 = blockIdx.y * BM;
    const int n0 = blockIdx.x * BN;

    const int warp = tid >> 5;
    const int lane = tid & 31;
    const int wm = (warp & 3) * 32;
    const int wn = (warp >> 2) * 64;
    const int g  = lane >> 2;
    const int tg = lane & 3;
    const int lrow16 = lane & 15;
    const int khalf  = (lane >> 4) << 3;

    // loader coords: 128 rows x 2 x 16B per operand
    const int lrow = tid >> 2;            // 0..63 (+64)
    const int lch  = (tid & 3) * 8;

    // fp16 accumulators: [i][j][h] = half2 {col nb, col nb+1} for row g + 8h
    uint32_t acc[2][8][2];
    #pragma unroll
    for (int i = 0; i < 2; i++)
        #pragma unroll
        for (int j = 0; j < 8; j++) {
            acc[i][j][0] = 0u;
            acc[i][j][1] = 0u;
        }

    const int NKT = DIM / BK;   // 8

    auto load_stage = [&](int kt, int st) {
        const int k0 = kt * BK;
        const uint32_t soff = (uint32_t)st * LSTG_BYTES;
        #pragma unroll
        for (int r = 0; r < 2; r++) {
            int row = lrow + r * 64;
            uint32_t d = soff + (uint32_t)(row * LDT + lch) * 2u;
            cp16s(base + d, &Xh[(size_t)(m0 + row) * DIM + k0 + lch], true);
            cp16s(base + boff0 + d,
                  &Ph[(size_t)(n0 + row) * DIM + k0 + lch], (n0 + row) < NCLS);
        }
        CP_COMMIT();
    };

    load_stage(0, 0);
    load_stage(1, 1);

    for (int kt = 0; kt < NKT; kt++) {
        if (kt < NKT - 1)
            asm volatile("cp.async.wait_group 1;\n" ::: "memory");
        else
            asm volatile("cp.async.wait_group 0;\n" ::: "memory");
        __syncthreads();

        const int st = kt & 1;
        const uint32_t ab = base + (uint32_t)st * LSTG_BYTES;
        const uint32_t bb = base + boff0 + (uint32_t)st * LSTG_BYTES;

        #pragma unroll
        for (int ks = 0; ks < 2; ks++) {
            const int kc = ks * 16 + khalf;
            uint32_t a[2][4];
            #pragma unroll
            for (int i = 0; i < 2; i++)
                ldm_x4(a[i][0], a[i][1], a[i][2], a[i][3],
                       ab + (uint32_t)((wm + i * 16 + lrow16) * LDT + kc) * 2u);
            #pragma unroll
            for (int jj = 0; jj < 4; jj++) {
                uint32_t b0, b1, b2, b3;
                ldm_x4(b0, b1, b2, b3,
                       bb + (uint32_t)((wn + jj * 16 + lrow16) * LDT + kc) * 2u);
                #pragma unroll
                for (int i = 0; i < 2; i++) {
                    mma16816h(acc[i][2 * jj + 0][0], acc[i][2 * jj + 0][1],
                              a[i][0], a[i][1], a[i][2], a[i][3], b0, b2);
                    mma16816h(acc[i][2 * jj + 1][0], acc[i][2 * jj + 1][1],
                              a[i][0], a[i][1], a[i][2], a[i][3], b1, b3);
                }
            }
        }
        __syncthreads();                      // stage consumed by all warps
        if (kt + 2 < NKT) load_stage(kt + 2, st);
    }

    // ---- Poincare epilogue (approx MUFU math, hoisted reciprocals)
    const float lscale = fminf(expf(logit_scale[0]), 100.f);

    float xs[2][2], rx[2][2];
    #pragma unroll
    for (int i = 0; i < 2; i++)
        #pragma unroll
        for (int h = 0; h < 2; h++) {
            const int m = m0 + wm + i * 16 + g + h * 8;
            xs[i][h] = xsq[m];
            rx[i][h] = frcp_approx(fmaxf(1.f - xs[i][h], 0.f));  // +inf ok
        }

    #pragma unroll
    for (int j = 0; j < 8; j++) {
        const int nb = n0 + wn + j * 8 + tg * 2;
        if (nb >= NCLS) continue;              // NCLS even -> pairs in/out together
        const float ps0 = psq[nb], ps1 = psq[nb + 1];
        const float rp0 = frcp_approx(fmaxf(1.f - ps0, 0.f));
        const float rp1 = frcp_approx(fmaxf(1.f - ps1, 0.f));
        #pragma unroll
        for (int i = 0; i < 2; i++) {
            #pragma unroll
            for (int h = 0; h < 2; h++) {
                const int m = m0 + wm + i * 16 + g + h * 8;
                const float xsv = xs[i][h];
                const float rxv = rx[i][h];

                const float2 xp = __half22float2(*(__half2*)&acc[i][j][h]);
                float d0 = fmaxf(xsv + ps0 - 2.f * xp.x, 0.f);
                float d1 = fmaxf(xsv + ps1 - 2.f * xp.y, 0.f);
                // 1/max(omx*omp, eps) == min(rcp(omx)*rcp(omp), 1/eps)
                float rr0 = fminf(rxv * rp0, INV_EPS);
                float rr1 = fminf(rxv * rp1, INV_EPS);
                float a0 = fmaxf(fmaf(2.f * d0, rr0, 1.f), 1.f + EPS_F);
                float a1 = fmaxf(fmaf(2.f * d1, rr1, 1.f), 1.f + EPS_F);
                float r0 = __logf(a0 + fsqrt_approx(fmaf(a0, a0, -1.f)));
                float r1 = __logf(a1 + fsqrt_approx(fmaf(a1, a1, -1.f)));
                float2 v = make_float2(-r0 * lscale, -r1 * lscale);
                *(float2*)&Out[(size_t)m * NCLS + nb] = v;
            }
        }
    }
}

// ---------------------------------------------------------------------------
// Launch
// ---------------------------------------------------------------------------
extern "C" void kernel_launch(void* const* d_in, const int* in_sizes, int n_in,
                              void* d_out, int out_size)
{
    const float* features    = (const float*)d_in[0];
    const float* W           = (const float*)d_in[1];
    const float* bias        = (const float*)d_in[2];
    const float* embeddings  = (const float*)d_in[3];
    const float* logit_scale = (const float*)d_in[4];
    float* out = (float*)d_out;

    __half *xh, *ph;
    float *xsq, *psq;
    cudaGetSymbolAddress((void**)&xh,  g_xh);
    cudaGetSymbolAddress((void**)&xsq, g_xsq);
    cudaGetSymbolAddress((void**)&ph,  g_ph);
    cudaGetSymbolAddress((void**)&psq, g_psq);

    // 1. Fused proj (W-resident smem, single-sync mainloop) -> xh, xsq
    cudaFuncSetAttribute(proj_expmap_kernel,
                         cudaFuncAttributeMaxDynamicSharedMemorySize, PROJ_SMEM);
    proj_expmap_kernel<<<MROWS / PM, 512, PROJ_SMEM>>>(features, W, bias, xh, xsq);

    // 2. expmap0 on embeddings (warp-per-row) -> ph, psq
    expmap_kernel<<<(NCLS + 7) / 8, 256>>>(embeddings, ph, psq);

    // 3. Logits GEMM (fp16, BK=32 2-stage, 4 CTA/SM) + approx Poincare epilogue
    cudaFuncSetAttribute(logits_mma_kernel,
                         cudaFuncAttributeMaxDynamicSharedMemorySize, LOGITS_SMEM);
    {
        dim3 grid((NCLS + BN - 1) / BN, MROWS / BM);   // (8, 256)
        logits_mma_kernel<<<grid, 256, LOGITS_SMEM>>>(xh, ph, xsq, psq,
                                                      logit_scale, out);
    }
}